// round 15
// baseline (speedup 1.0000x reference)
#include <cuda_runtime.h>
#include <cuda_bf16.h>
#include <cuda_fp8.h>
#include <math.h>
#include <stdint.h>

#define STU_NUM 100000
#define PROB_NUM 20000
#define KNOW_NUM 128
#define DIM 128
#define BATCH 8192
#define HIDDEN 512

// fp8 static scales: activations x64, weights x16 -> every GEMM acc carries 1024
#define ACT_SCALE 64.0f
#define W_SCALE 16.0f
#define INV_SCALE (1.0f / (ACT_SCALE * W_SCALE))

// ---------------------------------------------------------------------------
// Scratch (__device__ globals; allocation-free rule)
// ---------------------------------------------------------------------------
__device__ uint8_t g_state[BATCH * KNOW_NUM];        // fp8 e4m3, x64
__device__ uint8_t g_h1[BATCH * HIDDEN];             // fp8 e4m3, x64
__device__ uint8_t g_h2[BATCH * (HIDDEN / 2)];       // fp8 e4m3, x64
__device__ float g_knowS[KNOW_NUM * DIM];            // round(know * w_stat), tf32
__device__ float g_knowK[KNOW_NUM * DIM];            // round(know * w_kdiff), tf32
__device__ uint8_t g_W1t[HIDDEN * KNOW_NUM];         // [512,128] K-major fp8, x16
__device__ uint8_t g_W2t[(HIDDEN / 2) * HIDDEN];     // x16
__device__ uint8_t g_W3t[(HIDDEN / 4) * (HIDDEN / 2)]; // x16

// Fast transcendentals: ex2.approx-based, rel err ~1e-6.
__device__ __forceinline__ float fast_sigmoid(float x) {
    return __fdividef(1.0f, 1.0f + __expf(-x));
}
__device__ __forceinline__ float fast_tanh(float x) {
    float e = __expf(2.0f * x);
    return __fdividef(e - 1.0f, e + 1.0f);
}

__device__ __forceinline__ float tf32r(float x) {
    uint32_t u;
    asm("cvt.rna.tf32.f32 %0, %1;" : "=r"(u) : "f"(x));
    return __uint_as_float(u);
}

__device__ __forceinline__ uint16_t fp8x2(float x, float y) {
    return (uint16_t)__nv_cvt_float2_to_fp8x2(make_float2(x, y), __NV_SATFINITE, __NV_E4M3);
}

__device__ __forceinline__ uint32_t smem_u32(const void* p) {
    uint32_t a;
    asm("{ .reg .u64 t; cvta.to.shared.u64 t, %1; cvt.u32.u64 %0, t; }"
        : "=r"(a) : "l"(p));
    return a;
}

#define CP_ASYNC16(dst, src) \
    asm volatile("cp.async.cg.shared.global [%0], [%1], 16;" :: "r"(dst), "l"(src) : "memory")
#define CP_COMMIT() asm volatile("cp.async.commit_group;" ::: "memory")

#define LDSM_X4(r0, r1, r2, r3, addr) \
    asm volatile("ldmatrix.sync.aligned.m8n8.x4.shared.b16 {%0,%1,%2,%3}, [%4];" \
        : "=r"(r0), "=r"(r1), "=r"(r2), "=r"(r3) : "r"(addr))

// m16n8k8 tf32 mma (fused1 only)
__device__ __forceinline__ void mma_tf32(float* c, const uint32_t a[4],
                                         uint32_t b0, uint32_t b1) {
    asm volatile(
        "mma.sync.aligned.m16n8k8.row.col.f32.tf32.tf32.f32 "
        "{%0,%1,%2,%3}, {%4,%5,%6,%7}, {%8,%9}, {%0,%1,%2,%3};"
        : "+f"(c[0]), "+f"(c[1]), "+f"(c[2]), "+f"(c[3])
        : "r"(a[0]), "r"(a[1]), "r"(a[2]), "r"(a[3]), "r"(b0), "r"(b1));
}

// m16n8k32 e4m3 mma: A row-major, B col-major, fp32 accumulate
__device__ __forceinline__ void mma_fp8(float* c, const uint32_t a[4],
                                        uint32_t b0, uint32_t b1) {
    asm volatile(
        "mma.sync.aligned.m16n8k32.row.col.f32.e4m3.e4m3.f32 "
        "{%0,%1,%2,%3}, {%4,%5,%6,%7}, {%8,%9}, {%0,%1,%2,%3};"
        : "+f"(c[0]), "+f"(c[1]), "+f"(c[2]), "+f"(c[3])
        : "r"(a[0]), "r"(a[1]), "r"(a[2]), "r"(a[3]), "r"(b0), "r"(b1));
}

#define ROWSTRIDE 36       // fp32 path (fused1)
#define BRS 20             // fp8 path: 64-byte row = 16 u32 + 4 pad (conflict-free)

// ---------------------------------------------------------------------------
// Prep: transpose W1/W2/W3 to K-major fp8 (x16); tf32-scaled knowledge mats.
// ---------------------------------------------------------------------------
__global__ void prep_kernel(const float* __restrict__ W1, const float* __restrict__ W2,
                            const float* __restrict__ W3, const float* __restrict__ know,
                            const float* __restrict__ w_stat, const float* __restrict__ w_kdiff,
                            uint8_t* __restrict__ W1t, uint8_t* __restrict__ W2t,
                            uint8_t* __restrict__ W3t, float* __restrict__ knowS,
                            float* __restrict__ knowK) {
    __shared__ float t[32][33];
    const int z = blockIdx.z;
    if (z == 3) {
        int idx = (blockIdx.y * gridDim.x + blockIdx.x) * 256 + threadIdx.y * 32 + threadIdx.x;
        if (idx < KNOW_NUM * DIM) {
            float v = know[idx];
            int d = idx & (DIM - 1);
            knowS[idx] = tf32r(v * w_stat[d]);
            knowK[idx] = tf32r(v * w_kdiff[d]);
        }
        return;
    }
    const float* in; uint8_t* out; int K, N;
    if (z == 0) { in = W1; out = W1t; K = KNOW_NUM; N = HIDDEN; }
    else if (z == 1) { in = W2; out = W2t; K = HIDDEN; N = HIDDEN / 2; }
    else { in = W3; out = W3t; K = HIDDEN / 2; N = HIDDEN / 4; }
    const int bx = blockIdx.x, by = blockIdx.y;
    if (bx * 32 >= N || by * 32 >= K) return;
    const int x = bx * 32 + threadIdx.x;
#pragma unroll
    for (int i = 0; i < 32; i += 8) {
        int y = by * 32 + threadIdx.y + i;
        t[threadIdx.y + i][threadIdx.x] = in[(size_t)y * N + x];
    }
    __syncthreads();
    const int xo = by * 32 + threadIdx.x;
#pragma unroll
    for (int i = 0; i < 32; i += 8) {
        int yo = bx * 32 + threadIdx.y + i;
        float v = t[threadIdx.x][threadIdx.y + i] * W_SCALE;
        out[(size_t)yo * K + xo] =
            (uint8_t)__nv_cvt_float_to_fp8(v, __NV_SATFINITE, __NV_E4M3);
    }
}

// ---------------------------------------------------------------------------
// Fused kernel 1: gather + dual tf32 GEMM + combine -> fp8 state (x64).
// (unchanged)
// ---------------------------------------------------------------------------
#define F1_AS_OFF 0
#define F1_AK_OFF (64 * ROWSTRIDE)
#define F1_BS_OFF (128 * ROWSTRIDE)
#define F1_BK_OFF (256 * ROWSTRIDE)
#define F1_STAGE_FLOATS (384 * ROWSTRIDE)
#define F1_STAGE_BYTES  (F1_STAGE_FLOATS * 4)
#define F1_NSTAGES 3
#define F1_DYN_SMEM (F1_NSTAGES * F1_STAGE_BYTES)    // 165888

__device__ __forceinline__ void f1_stage(const float* __restrict__ z,
                                         const int* sidS, const int* eidS,
                                         const float* __restrict__ knowS,
                                         const float* __restrict__ knowK,
                                         int k0, uint32_t sbase, int tid) {
#pragma unroll
    for (int i = 0; i < 12; i++) {
        int idx = tid + i * 256;
        if (idx < 512) {
            int r = idx >> 3, c4 = idx & 7;
            uint32_t off = (uint32_t)(F1_AS_OFF + r * ROWSTRIDE + c4 * 4) * 4u;
            CP_ASYNC16(sbase + off, z + (size_t)sidS[r] * DIM + k0 + c4 * 4);
        } else if (idx < 1024) {
            int t = idx - 512;
            int r = t >> 3, c4 = t & 7;
            uint32_t off = (uint32_t)(F1_AK_OFF + r * ROWSTRIDE + c4 * 4) * 4u;
            CP_ASYNC16(sbase + off, z + (size_t)eidS[r] * DIM + k0 + c4 * 4);
        } else if (idx < 2048) {
            int t = idx - 1024;
            int r = t >> 3, c4 = t & 7;
            uint32_t off = (uint32_t)(F1_BS_OFF + r * ROWSTRIDE + c4 * 4) * 4u;
            CP_ASYNC16(sbase + off, knowS + (size_t)r * DIM + k0 + c4 * 4);
        } else {
            int t = idx - 2048;
            int r = t >> 3, c4 = t & 7;
            uint32_t off = (uint32_t)(F1_BK_OFF + r * ROWSTRIDE + c4 * 4) * 4u;
            CP_ASYNC16(sbase + off, knowK + (size_t)r * DIM + k0 + c4 * 4);
        }
    }
    CP_COMMIT();
}

__global__ __launch_bounds__(256, 1) void fused1_kernel(
    const float* __restrict__ z, const int* __restrict__ sid, const int* __restrict__ eid,
    const float* __restrict__ knowS, const float* __restrict__ knowK,
    const float* __restrict__ kp, const float* __restrict__ b_stat,
    const float* __restrict__ b_kdiff, uint8_t* __restrict__ state) {
    extern __shared__ __align__(16) char dyn[];
    __shared__ int sidS[64], eidS[64];
    const uint32_t sbase = smem_u32(dyn);
    const uint32_t* smem_u = reinterpret_cast<const uint32_t*>(dyn);

    const int tid = threadIdx.x;
    const int m0 = blockIdx.x * 64;
    if (tid < 64) sidS[tid] = sid[m0 + tid];
    else if (tid < 128) eidS[tid - 64] = eid[m0 + tid - 64];
    __syncthreads();

    const int wid = tid >> 5, lane = tid & 31;
    const int g = lane >> 2, tig = lane & 3;
    const int wm = (wid & 1) * 32;
    const int wn = (wid >> 1) * 32;

    float accS[2][4][4], accK[2][4][4];
#pragma unroll
    for (int i = 0; i < 2; i++)
#pragma unroll
        for (int j = 0; j < 4; j++)
#pragma unroll
            for (int q = 0; q < 4; q++) { accS[i][j][q] = 0.0f; accK[i][j][q] = 0.0f; }

    f1_stage(z, sidS, eidS, knowS, knowK, 0, sbase, tid);
    f1_stage(z, sidS, eidS, knowS, knowK, 32, sbase + F1_STAGE_BYTES, tid);

    const int Cn = DIM / 32;   // 4
    for (int c = 0; c < Cn; c++) {
        if (c + 1 < Cn) asm volatile("cp.async.wait_group 1;" ::: "memory");
        else            asm volatile("cp.async.wait_group 0;" ::: "memory");
        __syncthreads();
        if (c + 2 < Cn) {
            int buf = (c + 2) % F1_NSTAGES;
            f1_stage(z, sidS, eidS, knowS, knowK, (c + 2) * 32,
                     sbase + buf * F1_STAGE_BYTES, tid);
        }
        const uint32_t* St = smem_u + (c % F1_NSTAGES) * F1_STAGE_FLOATS;

#pragma unroll
        for (int kk = 0; kk < 4; kk++) {
            const int kb = kk * 8;
            uint32_t aS[2][4], aK[2][4];
#pragma unroll
            for (int i = 0; i < 2; i++) {
                const int m = wm + i * 16 + g;
                aS[i][0] = St[F1_AS_OFF + m * ROWSTRIDE + kb + tig];
                aS[i][1] = St[F1_AS_OFF + (m + 8) * ROWSTRIDE + kb + tig];
                aS[i][2] = St[F1_AS_OFF + m * ROWSTRIDE + kb + tig + 4];
                aS[i][3] = St[F1_AS_OFF + (m + 8) * ROWSTRIDE + kb + tig + 4];
                aK[i][0] = St[F1_AK_OFF + m * ROWSTRIDE + kb + tig];
                aK[i][1] = St[F1_AK_OFF + (m + 8) * ROWSTRIDE + kb + tig];
                aK[i][2] = St[F1_AK_OFF + m * ROWSTRIDE + kb + tig + 4];
                aK[i][3] = St[F1_AK_OFF + (m + 8) * ROWSTRIDE + kb + tig + 4];
            }
#pragma unroll
            for (int j = 0; j < 4; j++) {
                const int n = wn + j * 8 + g;
                uint32_t bS0 = St[F1_BS_OFF + n * ROWSTRIDE + kb + tig];
                uint32_t bS1 = St[F1_BS_OFF + n * ROWSTRIDE + kb + tig + 4];
                uint32_t bK0 = St[F1_BK_OFF + n * ROWSTRIDE + kb + tig];
                uint32_t bK1 = St[F1_BK_OFF + n * ROWSTRIDE + kb + tig + 4];
                mma_tf32(accS[0][j], aS[0], bS0, bS1);
                mma_tf32(accS[1][j], aS[1], bS0, bS1);
                mma_tf32(accK[0][j], aK[0], bK0, bK1);
                mma_tf32(accK[1][j], aK[1], bK0, bK1);
            }
        }
    }

    // Epilogue: state(fp8) = ACT_SCALE * kp * (sig(Ps+bs) - sig(Pk+bk))
    const float bs = b_stat[0], bk = b_kdiff[0];
#pragma unroll
    for (int i = 0; i < 2; i++) {
        const int r0 = m0 + wm + i * 16 + g;
#pragma unroll
        for (int j = 0; j < 4; j++) {
            const int col = wn + j * 8 + tig * 2;
            float2 kpa = *reinterpret_cast<const float2*>(kp + (size_t)r0 * KNOW_NUM + col);
            float2 kpb = *reinterpret_cast<const float2*>(kp + (size_t)(r0 + 8) * KNOW_NUM + col);
            uint16_t lo = fp8x2(
                ACT_SCALE * kpa.x * (fast_sigmoid(accS[i][j][0] + bs) - fast_sigmoid(accK[i][j][0] + bk)),
                ACT_SCALE * kpa.y * (fast_sigmoid(accS[i][j][1] + bs) - fast_sigmoid(accK[i][j][1] + bk)));
            uint16_t hi = fp8x2(
                ACT_SCALE * kpb.x * (fast_sigmoid(accS[i][j][2] + bs) - fast_sigmoid(accK[i][j][2] + bk)),
                ACT_SCALE * kpb.y * (fast_sigmoid(accS[i][j][3] + bs) - fast_sigmoid(accK[i][j][3] + bk)));
            *reinterpret_cast<uint16_t*>(state + (size_t)r0 * KNOW_NUM + col) = lo;
            *reinterpret_cast<uint16_t*>(state + (size_t)(r0 + 8) * KNOW_NUM + col) = hi;
        }
    }
}

// ---------------------------------------------------------------------------
// fp8 GEMM, wide warp tile: CTA 64x128, 128 threads (4 warps 2m x 2n,
// warp 32x64), BK=64 elems, 4-stage cp.async, ldmatrix fragment loads.
// C(fp8,x64) = ACT_SCALE * tanh(INV_SCALE * acc + bias)
// ---------------------------------------------------------------------------
#define G_STAGE_U32   ((64 + 128) * BRS)             // 3840 u32
#define G_STAGE_BYTES (G_STAGE_U32 * 4)              // 15360
#define G_NSTAGES 4
#define G_DYN_SMEM    (G_NSTAGES * G_STAGE_BYTES)    // 61440

__device__ __forceinline__ void g_stage_f8(const uint8_t* __restrict__ A,
                                           const uint8_t* __restrict__ Bt,
                                           int K, int m0, int n0, int k0,
                                           uint32_t sbase, int tid) {
    const uint32_t sB = sbase + 64 * BRS * 4;
#pragma unroll
    for (int i = 0; i < 6; i++) {
        int idx = tid + i * 128;              // 0..767
        if (idx < 256) {
            int r = idx >> 2, c4 = idx & 3;
            uint32_t off = (uint32_t)(r * BRS + c4 * 4) * 4u;
            CP_ASYNC16(sbase + off, A + (size_t)(m0 + r) * K + k0 + c4 * 16);
        } else {
            int t = idx - 256;                // 0..511
            int r = t >> 2, c4 = t & 3;
            uint32_t off = (uint32_t)(r * BRS + c4 * 4) * 4u;
            CP_ASYNC16(sB + off, Bt + (size_t)(n0 + r) * K + k0 + c4 * 16);
        }
    }
    CP_COMMIT();
}

__global__ __launch_bounds__(128, 3) void mma_gemm_f8(const uint8_t* __restrict__ A,
                                                      const uint8_t* __restrict__ Bt,
                                                      const float* __restrict__ bias,
                                                      uint8_t* __restrict__ C,
                                                      int M, int N, int K) {
    extern __shared__ __align__(16) char dyn[];
    const uint32_t sbase = smem_u32(dyn);

    const int tid = threadIdx.x;
    const int wid = tid >> 5;
    const int lane = tid & 31;
    const int g = lane >> 2, tig = lane & 3;
    const int wm = (wid & 1) * 32;        // 2 warps in M
    const int wn = (wid >> 1) * 64;       // 2 warps in N, warp covers 64 cols
    const int m0 = blockIdx.y * 64, n0 = blockIdx.x * 128;
    const int Cn = K >> 6;                // 64-element chunks

    // ldmatrix per-lane byte offsets
    const uint32_t aoff0 = (uint32_t)((wm + (lane & 15)) * BRS + (lane >> 4) * 4) * 4u;
    const uint32_t aoff1 = aoff0 + 16u * BRS * 4u;
    const uint32_t boff0 = (uint32_t)((wn + ((lane >> 4) << 3) + (lane & 7)) * BRS +
                                      ((lane >> 3) & 1) * 4) * 4u;

    float acc[2][8][4];
#pragma unroll
    for (int i = 0; i < 2; i++)
#pragma unroll
        for (int j = 0; j < 8; j++)
#pragma unroll
            for (int q = 0; q < 4; q++) acc[i][j][q] = 0.0f;

    g_stage_f8(A, Bt, K, m0, n0, 0, sbase, tid);
    if (Cn > 1) g_stage_f8(A, Bt, K, m0, n0, 64, sbase + G_STAGE_BYTES, tid);
    if (Cn > 2) g_stage_f8(A, Bt, K, m0, n0, 128, sbase + 2 * G_STAGE_BYTES, tid);

    for (int c = 0; c < Cn; c++) {
        if (c < Cn - 2)       asm volatile("cp.async.wait_group 2;" ::: "memory");
        else if (c == Cn - 2) asm volatile("cp.async.wait_group 1;" ::: "memory");
        else                  asm volatile("cp.async.wait_group 0;" ::: "memory");
        __syncthreads();
        if (c + 3 < Cn)
            g_stage_f8(A, Bt, K, m0, n0, (c + 3) * 64,
                       sbase + ((c + 3) & 3) * G_STAGE_BYTES, tid);

        const uint32_t As = sbase + (c & 3) * G_STAGE_BYTES;
        const uint32_t Bs = As + 64 * BRS * 4;

        uint32_t af[2][2][4], bf[2][8][2];
#pragma unroll
        for (int kk = 0; kk < 2; kk++) {
            const uint32_t kby = kk * 32u;   // 8 u32 = 32 bytes per k-step
            LDSM_X4(af[kk][0][0], af[kk][0][1], af[kk][0][2], af[kk][0][3], As + aoff0 + kby);
            LDSM_X4(af[kk][1][0], af[kk][1][1], af[kk][1][2], af[kk][1][3], As + aoff1 + kby);
#pragma unroll
            for (int p = 0; p < 4; p++) {
                const uint32_t bo = boff0 + (uint32_t)p * 16u * BRS * 4u + kby;
                LDSM_X4(bf[kk][2 * p][0], bf[kk][2 * p][1],
                        bf[kk][2 * p + 1][0], bf[kk][2 * p + 1][1], Bs + bo);
            }
        }
#pragma unroll
        for (int kk = 0; kk < 2; kk++) {
#pragma unroll
            for (int j = 0; j < 8; j++) {
                mma_fp8(acc[0][j], af[kk][0], bf[kk][j][0], bf[kk][j][1]);
                mma_fp8(acc[1][j], af[kk][1], bf[kk][j][0], bf[kk][j][1]);
            }
        }
    }

#pragma unroll
    for (int i = 0; i < 2; i++) {
        const int row0 = m0 + wm + i * 16 + g;
#pragma unroll
        for (int j = 0; j < 8; j++) {
            const int col = n0 + wn + j * 8 + tig * 2;
            float bx0 = bias[col], bx1 = bias[col + 1];
            uint16_t lo = fp8x2(
                ACT_SCALE * fast_tanh(INV_SCALE * acc[i][j][0] + bx0),
                ACT_SCALE * fast_tanh(INV_SCALE * acc[i][j][1] + bx1));
            uint16_t hi = fp8x2(
                ACT_SCALE * fast_tanh(INV_SCALE * acc[i][j][2] + bx0),
                ACT_SCALE * fast_tanh(INV_SCALE * acc[i][j][3] + bx1));
            *reinterpret_cast<uint16_t*>(C + (size_t)row0 * N + col) = lo;
            *reinterpret_cast<uint16_t*>(C + (size_t)(row0 + 8) * N + col) = hi;
        }
    }
}

// ---------------------------------------------------------------------------
// Fused kernel D (fp8, ldmatrix): h3 GEMM (tile 32x128, K=256) + final dot.
// 128 threads (4 warps 1m x 4n), grid = BATCH/32 = 256 CTAs. (unchanged)
// ---------------------------------------------------------------------------
#define GD_STAGE_U32   (160 * BRS)                   // 3200 u32
#define GD_STAGE_BYTES (GD_STAGE_U32 * 4)            // 12800
#define GD_NSTAGES 4
#define GD_DYN_SMEM    (GD_NSTAGES * GD_STAGE_BYTES + 512)   // 51712

__device__ __forceinline__ void gd_stage_f8(const uint8_t* __restrict__ A,
                                            const uint8_t* __restrict__ Bt,
                                            int K, int m0, int k0,
                                            uint32_t sbase, int tid) {
    const uint32_t sB = sbase + 32 * BRS * 4;
#pragma unroll
    for (int i = 0; i < 5; i++) {
        int idx = tid + i * 128;              // 0..639
        if (idx < 128) {
            int r = idx >> 2, c4 = idx & 3;
            uint32_t off = (uint32_t)(r * BRS + c4 * 4) * 4u;
            CP_ASYNC16(sbase + off, A + (size_t)(m0 + r) * K + k0 + c4 * 16);
        } else {
            int t = idx - 128;
            int r = t >> 2, c4 = t & 3;
            uint32_t off = (uint32_t)(r * BRS + c4 * 4) * 4u;
            CP_ASYNC16(sB + off, Bt + (size_t)r * K + k0 + c4 * 16);
        }
    }
    CP_COMMIT();
}

__global__ __launch_bounds__(128, 4) void gemm3_final_kernel(
    const uint8_t* __restrict__ A, const uint8_t* __restrict__ Bt,
    const float* __restrict__ bias, const float* __restrict__ W4,
    const float* __restrict__ b4, float* __restrict__ out) {
    extern __shared__ __align__(16) char dyn[];
    const uint32_t sbase = smem_u32(dyn);
    float* sred = reinterpret_cast<float*>(dyn + GD_NSTAGES * GD_STAGE_BYTES);  // [32][4]

    const int K = HIDDEN / 2;   // 256
    const int tid = threadIdx.x;
    const int wid = tid >> 5;
    const int lane = tid & 31;
    const int g = lane >> 2, tig = lane & 3;
    const int wn = wid * 32;
    const int m0 = blockIdx.x * 32;
    const int Cn = K >> 6;   // 4

    const uint32_t aoff0 = (uint32_t)((lane & 15) * BRS + (lane >> 4) * 4) * 4u;
    const uint32_t aoff1 = aoff0 + 16u * BRS * 4u;
    const uint32_t boff0 = (uint32_t)((wn + ((lane >> 4) << 3) + (lane & 7)) * BRS +
                                      ((lane >> 3) & 1) * 4) * 4u;
    const uint32_t boff1 = boff0 + 16u * BRS * 4u;

    float acc[2][4][4];
#pragma unroll
    for (int i = 0; i < 2; i++)
#pragma unroll
        for (int j = 0; j < 4; j++)
#pragma unroll
            for (int q = 0; q < 4; q++) acc[i][j][q] = 0.0f;

    gd_stage_f8(A, Bt, K, m0, 0, sbase, tid);
    gd_stage_f8(A, Bt, K, m0, 64, sbase + GD_STAGE_BYTES, tid);
    gd_stage_f8(A, Bt, K, m0, 128, sbase + 2 * GD_STAGE_BYTES, tid);

    for (int c = 0; c < Cn; c++) {
        if (c < Cn - 2)       asm volatile("cp.async.wait_group 2;" ::: "memory");
        else if (c == Cn - 2) asm volatile("cp.async.wait_group 1;" ::: "memory");
        else                  asm volatile("cp.async.wait_group 0;" ::: "memory");
        __syncthreads();
        if (c + 3 < Cn)
            gd_stage_f8(A, Bt, K, m0, (c + 3) * 64,
                        sbase + ((c + 3) & 3) * GD_STAGE_BYTES, tid);

        const uint32_t As = sbase + (c & 3) * GD_STAGE_BYTES;
        const uint32_t Bs = As + 32 * BRS * 4;

        uint32_t af[2][2][4], bf[2][4][2];
#pragma unroll
        for (int kk = 0; kk < 2; kk++) {
            const uint32_t kby = kk * 32u;
            LDSM_X4(af[kk][0][0], af[kk][0][1], af[kk][0][2], af[kk][0][3], As + aoff0 + kby);
            LDSM_X4(af[kk][1][0], af[kk][1][1], af[kk][1][2], af[kk][1][3], As + aoff1 + kby);
            LDSM_X4(bf[kk][0][0], bf[kk][0][1], bf[kk][1][0], bf[kk][1][1], Bs + boff0 + kby);
            LDSM_X4(bf[kk][2][0], bf[kk][2][1], bf[kk][3][0], bf[kk][3][1], Bs + boff1 + kby);
        }
#pragma unroll
        for (int kk = 0; kk < 2; kk++) {
#pragma unroll
            for (int j = 0; j < 4; j++) {
                mma_fp8(acc[0][j], af[kk][0], bf[kk][j][0], bf[kk][j][1]);
                mma_fp8(acc[1][j], af[kk][1], bf[kk][j][0], bf[kk][j][1]);
            }
        }
    }

    // Fused reduction epilogue
    float part[2][2] = {{0.0f, 0.0f}, {0.0f, 0.0f}};
#pragma unroll
    for (int i = 0; i < 2; i++) {
#pragma unroll
        for (int j = 0; j < 4; j++) {
            const int col = wn + j * 8 + tig * 2;
            float w0 = W4[col], w1 = W4[col + 1];
            float bc0 = bias[col], bc1 = bias[col + 1];
            part[i][0] += fast_tanh(INV_SCALE * acc[i][j][0] + bc0) * w0 +
                          fast_tanh(INV_SCALE * acc[i][j][1] + bc1) * w1;
            part[i][1] += fast_tanh(INV_SCALE * acc[i][j][2] + bc0) * w0 +
                          fast_tanh(INV_SCALE * acc[i][j][3] + bc1) * w1;
        }
    }
#pragma unroll
    for (int i = 0; i < 2; i++)
#pragma unroll
        for (int h = 0; h < 2; h++) {
            part[i][h] += __shfl_xor_sync(0xFFFFFFFFu, part[i][h], 1);
            part[i][h] += __shfl_xor_sync(0xFFFFFFFFu, part[i][h], 2);
        }
    if (tig == 0) {
#pragma unroll
        for (int i = 0; i < 2; i++)
#pragma unroll
            for (int h = 0; h < 2; h++)
                sred[(i * 16 + g + h * 8) * 4 + wid] = part[i][h];
    }
    __syncthreads();
    if (tid < 32) {
        float s = sred[tid * 4] + sred[tid * 4 + 1] + sred[tid * 4 + 2] +
                  sred[tid * 4 + 3] + b4[0];
        out[m0 + tid] = fast_sigmoid(s);
    }
}

// ---------------------------------------------------------------------------
// Launch
// ---------------------------------------------------------------------------
extern "C" void kernel_launch(void* const* d_in, const int* in_sizes, int n_in,
                              void* d_out, int out_size) {
    const float* z       = (const float*)d_in[0];
    const int*   sid     = (const int*)d_in[1];
    const int*   eid     = (const int*)d_in[2];
    const float* kp      = (const float*)d_in[3];
    const float* w_stat  = (const float*)d_in[4];
    const float* b_stat  = (const float*)d_in[5];
    const float* w_kdiff = (const float*)d_in[6];
    const float* b_kdiff = (const float*)d_in[7];
    const float* W1      = (const float*)d_in[8];
    const float* b1      = (const float*)d_in[9];
    const float* W2      = (const float*)d_in[10];
    const float* b2      = (const float*)d_in[11];
    const float* W3      = (const float*)d_in[12];
    const float* b3      = (const float*)d_in[13];
    const float* W4      = (const float*)d_in[14];
    const float* b4      = (const float*)d_in[15];
    float* out = (float*)d_out;

    uint8_t *pState, *pH1, *pH2, *pW1t, *pW2t, *pW3t;
    float *pKnowS, *pKnowK;
    cudaGetSymbolAddress((void**)&pState, g_state);
    cudaGetSymbolAddress((void**)&pH1, g_h1);
    cudaGetSymbolAddress((void**)&pH2, g_h2);
    cudaGetSymbolAddress((void**)&pKnowS, g_knowS);
    cudaGetSymbolAddress((void**)&pKnowK, g_knowK);
    cudaGetSymbolAddress((void**)&pW1t, g_W1t);
    cudaGetSymbolAddress((void**)&pW2t, g_W2t);
    cudaGetSymbolAddress((void**)&pW3t, g_W3t);

    const float* know = z + (size_t)(STU_NUM + PROB_NUM) * DIM;

    static bool attr_set = false;
    if (!attr_set) {
        cudaFuncSetAttribute(fused1_kernel, cudaFuncAttributeMaxDynamicSharedMemorySize, F1_DYN_SMEM);
        cudaFuncSetAttribute(mma_gemm_f8, cudaFuncAttributeMaxDynamicSharedMemorySize, G_DYN_SMEM);
        cudaFuncSetAttribute(gemm3_final_kernel, cudaFuncAttributeMaxDynamicSharedMemorySize, GD_DYN_SMEM);
        attr_set = true;
    }

    // 1. prep
    prep_kernel<<<dim3(16, 16, 4), dim3(32, 8)>>>(W1, W2, W3, know, w_stat, w_kdiff,
                                                  pW1t, pW2t, pW3t, pKnowS, pKnowK);

    // 2. fused gather + dual GEMM + combine -> state (fp8 x64)
    fused1_kernel<<<BATCH / 64, 256, F1_DYN_SMEM>>>(z, sid, eid, pKnowS, pKnowK,
                                                    kp, b_stat, b_kdiff, pState);

    // 3. h1 = tanh(state @ W1 + b1)   (8192 x 512 x 128) — 512 CTAs
    mma_gemm_f8<<<dim3(4, 128), 128, G_DYN_SMEM>>>(pState, pW1t, b1, pH1,
                                                   BATCH, HIDDEN, KNOW_NUM);

    // 4. h2 = tanh(h1 @ W2 + b2)      (8192 x 256 x 512) — 256 CTAs
    mma_gemm_f8<<<dim3(2, 128), 128, G_DYN_SMEM>>>(pH1, pW2t, b2, pH2,
                                                   BATCH, HIDDEN / 2, HIDDEN);

    // 5. fused h3 GEMM + final dot + sigmoid — 256 CTAs
    gemm3_final_kernel<<<BATCH / 32, 128, GD_DYN_SMEM>>>(pH2, pW3t, b3, W4, b4, out);
}

// round 16
// speedup vs baseline: 1.1000x; 1.1000x over previous
#include <cuda_runtime.h>
#include <cuda_bf16.h>
#include <cuda_fp8.h>
#include <math.h>
#include <stdint.h>

#define STU_NUM 100000
#define PROB_NUM 20000
#define KNOW_NUM 128
#define DIM 128
#define BATCH 8192
#define HIDDEN 512

// fp8 static scales: activations x64, weights x16 -> every GEMM acc carries 1024
#define ACT_SCALE 64.0f
#define W_SCALE 16.0f
#define INV_SCALE (1.0f / (ACT_SCALE * W_SCALE))

// ---------------------------------------------------------------------------
// Scratch (__device__ globals; allocation-free rule)
// ---------------------------------------------------------------------------
__device__ uint8_t g_state[BATCH * KNOW_NUM];        // fp8 e4m3, x64
__device__ float g_knowS[KNOW_NUM * DIM];            // round(know * w_stat), tf32
__device__ float g_knowK[KNOW_NUM * DIM];            // round(know * w_kdiff), tf32
__device__ uint8_t g_W1t[HIDDEN * KNOW_NUM];         // [512,128] K-major fp8, x16
__device__ uint8_t g_W2t[(HIDDEN / 2) * HIDDEN];     // x16
__device__ uint8_t g_W3t[(HIDDEN / 4) * (HIDDEN / 2)]; // x16

// Fast transcendentals: ex2.approx-based, rel err ~1e-6.
__device__ __forceinline__ float fast_sigmoid(float x) {
    return __fdividef(1.0f, 1.0f + __expf(-x));
}
__device__ __forceinline__ float fast_tanh(float x) {
    float e = __expf(2.0f * x);
    return __fdividef(e - 1.0f, e + 1.0f);
}

__device__ __forceinline__ float tf32r(float x) {
    uint32_t u;
    asm("cvt.rna.tf32.f32 %0, %1;" : "=r"(u) : "f"(x));
    return __uint_as_float(u);
}

__device__ __forceinline__ uint16_t fp8x2(float x, float y) {
    return (uint16_t)__nv_cvt_float2_to_fp8x2(make_float2(x, y), __NV_SATFINITE, __NV_E4M3);
}

__device__ __forceinline__ uint32_t smem_u32(const void* p) {
    uint32_t a;
    asm("{ .reg .u64 t; cvta.to.shared.u64 t, %1; cvt.u32.u64 %0, t; }"
        : "=r"(a) : "l"(p));
    return a;
}

#define CP_ASYNC16(dst, src) \
    asm volatile("cp.async.cg.shared.global [%0], [%1], 16;" :: "r"(dst), "l"(src) : "memory")
#define CP_COMMIT() asm volatile("cp.async.commit_group;" ::: "memory")

#define LDSM_X4(r0, r1, r2, r3, addr) \
    asm volatile("ldmatrix.sync.aligned.m8n8.x4.shared.b16 {%0,%1,%2,%3}, [%4];" \
        : "=r"(r0), "=r"(r1), "=r"(r2), "=r"(r3) : "r"(addr))

// m16n8k8 tf32 mma (fused1 only)
__device__ __forceinline__ void mma_tf32(float* c, const uint32_t a[4],
                                         uint32_t b0, uint32_t b1) {
    asm volatile(
        "mma.sync.aligned.m16n8k8.row.col.f32.tf32.tf32.f32 "
        "{%0,%1,%2,%3}, {%4,%5,%6,%7}, {%8,%9}, {%0,%1,%2,%3};"
        : "+f"(c[0]), "+f"(c[1]), "+f"(c[2]), "+f"(c[3])
        : "r"(a[0]), "r"(a[1]), "r"(a[2]), "r"(a[3]), "r"(b0), "r"(b1));
}

// m16n8k32 e4m3 mma: A row-major, B col-major, fp32 accumulate
__device__ __forceinline__ void mma_fp8(float* c, const uint32_t a[4],
                                        uint32_t b0, uint32_t b1) {
    asm volatile(
        "mma.sync.aligned.m16n8k32.row.col.f32.e4m3.e4m3.f32 "
        "{%0,%1,%2,%3}, {%4,%5,%6,%7}, {%8,%9}, {%0,%1,%2,%3};"
        : "+f"(c[0]), "+f"(c[1]), "+f"(c[2]), "+f"(c[3])
        : "r"(a[0]), "r"(a[1]), "r"(a[2]), "r"(a[3]), "r"(b0), "r"(b1));
}

#define ROWSTRIDE 36       // fp32 path (fused1)
#define BRS 20             // fp8 path: 64-byte row = 16 u32 + 4 pad (conflict-free)
#define CHUNK_B (64 * BRS * 4)     // 5120 bytes: one 64-row x 64-byte k-chunk

// ---------------------------------------------------------------------------
// Prep: transpose W1/W2/W3 to K-major fp8 (x16); tf32-scaled knowledge mats.
// ---------------------------------------------------------------------------
__global__ void prep_kernel(const float* __restrict__ W1, const float* __restrict__ W2,
                            const float* __restrict__ W3, const float* __restrict__ know,
                            const float* __restrict__ w_stat, const float* __restrict__ w_kdiff,
                            uint8_t* __restrict__ W1t, uint8_t* __restrict__ W2t,
                            uint8_t* __restrict__ W3t, float* __restrict__ knowS,
                            float* __restrict__ knowK) {
    __shared__ float t[32][33];
    const int z = blockIdx.z;
    if (z == 3) {
        int idx = (blockIdx.y * gridDim.x + blockIdx.x) * 256 + threadIdx.y * 32 + threadIdx.x;
        if (idx < KNOW_NUM * DIM) {
            float v = know[idx];
            int d = idx & (DIM - 1);
            knowS[idx] = tf32r(v * w_stat[d]);
            knowK[idx] = tf32r(v * w_kdiff[d]);
        }
        return;
    }
    const float* in; uint8_t* out; int K, N;
    if (z == 0) { in = W1; out = W1t; K = KNOW_NUM; N = HIDDEN; }
    else if (z == 1) { in = W2; out = W2t; K = HIDDEN; N = HIDDEN / 2; }
    else { in = W3; out = W3t; K = HIDDEN / 2; N = HIDDEN / 4; }
    const int bx = blockIdx.x, by = blockIdx.y;
    if (bx * 32 >= N || by * 32 >= K) return;
    const int x = bx * 32 + threadIdx.x;
#pragma unroll
    for (int i = 0; i < 32; i += 8) {
        int y = by * 32 + threadIdx.y + i;
        t[threadIdx.y + i][threadIdx.x] = in[(size_t)y * N + x];
    }
    __syncthreads();
    const int xo = by * 32 + threadIdx.x;
#pragma unroll
    for (int i = 0; i < 32; i += 8) {
        int yo = bx * 32 + threadIdx.y + i;
        float v = t[threadIdx.x][threadIdx.y + i] * W_SCALE;
        out[(size_t)yo * K + xo] =
            (uint8_t)__nv_cvt_float_to_fp8(v, __NV_SATFINITE, __NV_E4M3);
    }
}

// ---------------------------------------------------------------------------
// Fused kernel 1: gather + dual tf32 GEMM + combine -> fp8 state (x64).
// (unchanged from R14)
// ---------------------------------------------------------------------------
#define F1_AS_OFF 0
#define F1_AK_OFF (64 * ROWSTRIDE)
#define F1_BS_OFF (128 * ROWSTRIDE)
#define F1_BK_OFF (256 * ROWSTRIDE)
#define F1_STAGE_FLOATS (384 * ROWSTRIDE)
#define F1_STAGE_BYTES  (F1_STAGE_FLOATS * 4)
#define F1_NSTAGES 3
#define F1_DYN_SMEM (F1_NSTAGES * F1_STAGE_BYTES)    // 165888

__device__ __forceinline__ void f1_stage(const float* __restrict__ z,
                                         const int* sidS, const int* eidS,
                                         const float* __restrict__ knowS,
                                         const float* __restrict__ knowK,
                                         int k0, uint32_t sbase, int tid) {
#pragma unroll
    for (int i = 0; i < 12; i++) {
        int idx = tid + i * 256;
        if (idx < 512) {
            int r = idx >> 3, c4 = idx & 7;
            uint32_t off = (uint32_t)(F1_AS_OFF + r * ROWSTRIDE + c4 * 4) * 4u;
            CP_ASYNC16(sbase + off, z + (size_t)sidS[r] * DIM + k0 + c4 * 4);
        } else if (idx < 1024) {
            int t = idx - 512;
            int r = t >> 3, c4 = t & 7;
            uint32_t off = (uint32_t)(F1_AK_OFF + r * ROWSTRIDE + c4 * 4) * 4u;
            CP_ASYNC16(sbase + off, z + (size_t)eidS[r] * DIM + k0 + c4 * 4);
        } else if (idx < 2048) {
            int t = idx - 1024;
            int r = t >> 3, c4 = t & 7;
            uint32_t off = (uint32_t)(F1_BS_OFF + r * ROWSTRIDE + c4 * 4) * 4u;
            CP_ASYNC16(sbase + off, knowS + (size_t)r * DIM + k0 + c4 * 4);
        } else {
            int t = idx - 2048;
            int r = t >> 3, c4 = t & 7;
            uint32_t off = (uint32_t)(F1_BK_OFF + r * ROWSTRIDE + c4 * 4) * 4u;
            CP_ASYNC16(sbase + off, knowK + (size_t)r * DIM + k0 + c4 * 4);
        }
    }
    CP_COMMIT();
}

__global__ __launch_bounds__(256, 1) void fused1_kernel(
    const float* __restrict__ z, const int* __restrict__ sid, const int* __restrict__ eid,
    const float* __restrict__ knowS, const float* __restrict__ knowK,
    const float* __restrict__ kp, const float* __restrict__ b_stat,
    const float* __restrict__ b_kdiff, uint8_t* __restrict__ state) {
    extern __shared__ __align__(16) char dyn[];
    __shared__ int sidS[64], eidS[64];
    const uint32_t sbase = smem_u32(dyn);
    const uint32_t* smem_u = reinterpret_cast<const uint32_t*>(dyn);

    const int tid = threadIdx.x;
    const int m0 = blockIdx.x * 64;
    if (tid < 64) sidS[tid] = sid[m0 + tid];
    else if (tid < 128) eidS[tid - 64] = eid[m0 + tid - 64];
    __syncthreads();

    const int wid = tid >> 5, lane = tid & 31;
    const int g = lane >> 2, tig = lane & 3;
    const int wm = (wid & 1) * 32;
    const int wn = (wid >> 1) * 32;

    float accS[2][4][4], accK[2][4][4];
#pragma unroll
    for (int i = 0; i < 2; i++)
#pragma unroll
        for (int j = 0; j < 4; j++)
#pragma unroll
            for (int q = 0; q < 4; q++) { accS[i][j][q] = 0.0f; accK[i][j][q] = 0.0f; }

    f1_stage(z, sidS, eidS, knowS, knowK, 0, sbase, tid);
    f1_stage(z, sidS, eidS, knowS, knowK, 32, sbase + F1_STAGE_BYTES, tid);

    const int Cn = DIM / 32;   // 4
    for (int c = 0; c < Cn; c++) {
        if (c + 1 < Cn) asm volatile("cp.async.wait_group 1;" ::: "memory");
        else            asm volatile("cp.async.wait_group 0;" ::: "memory");
        __syncthreads();
        if (c + 2 < Cn) {
            int buf = (c + 2) % F1_NSTAGES;
            f1_stage(z, sidS, eidS, knowS, knowK, (c + 2) * 32,
                     sbase + buf * F1_STAGE_BYTES, tid);
        }
        const uint32_t* St = smem_u + (c % F1_NSTAGES) * F1_STAGE_FLOATS;

#pragma unroll
        for (int kk = 0; kk < 4; kk++) {
            const int kb = kk * 8;
            uint32_t aS[2][4], aK[2][4];
#pragma unroll
            for (int i = 0; i < 2; i++) {
                const int m = wm + i * 16 + g;
                aS[i][0] = St[F1_AS_OFF + m * ROWSTRIDE + kb + tig];
                aS[i][1] = St[F1_AS_OFF + (m + 8) * ROWSTRIDE + kb + tig];
                aS[i][2] = St[F1_AS_OFF + m * ROWSTRIDE + kb + tig + 4];
                aS[i][3] = St[F1_AS_OFF + (m + 8) * ROWSTRIDE + kb + tig + 4];
                aK[i][0] = St[F1_AK_OFF + m * ROWSTRIDE + kb + tig];
                aK[i][1] = St[F1_AK_OFF + (m + 8) * ROWSTRIDE + kb + tig];
                aK[i][2] = St[F1_AK_OFF + m * ROWSTRIDE + kb + tig + 4];
                aK[i][3] = St[F1_AK_OFF + (m + 8) * ROWSTRIDE + kb + tig + 4];
            }
#pragma unroll
            for (int j = 0; j < 4; j++) {
                const int n = wn + j * 8 + g;
                uint32_t bS0 = St[F1_BS_OFF + n * ROWSTRIDE + kb + tig];
                uint32_t bS1 = St[F1_BS_OFF + n * ROWSTRIDE + kb + tig + 4];
                uint32_t bK0 = St[F1_BK_OFF + n * ROWSTRIDE + kb + tig];
                uint32_t bK1 = St[F1_BK_OFF + n * ROWSTRIDE + kb + tig + 4];
                mma_tf32(accS[0][j], aS[0], bS0, bS1);
                mma_tf32(accS[1][j], aS[1], bS0, bS1);
                mma_tf32(accK[0][j], aK[0], bK0, bK1);
                mma_tf32(accK[1][j], aK[1], bK0, bK1);
            }
        }
    }

    const float bs = b_stat[0], bk = b_kdiff[0];
#pragma unroll
    for (int i = 0; i < 2; i++) {
        const int r0 = m0 + wm + i * 16 + g;
#pragma unroll
        for (int j = 0; j < 4; j++) {
            const int col = wn + j * 8 + tig * 2;
            float2 kpa = *reinterpret_cast<const float2*>(kp + (size_t)r0 * KNOW_NUM + col);
            float2 kpb = *reinterpret_cast<const float2*>(kp + (size_t)(r0 + 8) * KNOW_NUM + col);
            uint16_t lo = fp8x2(
                ACT_SCALE * kpa.x * (fast_sigmoid(accS[i][j][0] + bs) - fast_sigmoid(accK[i][j][0] + bk)),
                ACT_SCALE * kpa.y * (fast_sigmoid(accS[i][j][1] + bs) - fast_sigmoid(accK[i][j][1] + bk)));
            uint16_t hi = fp8x2(
                ACT_SCALE * kpb.x * (fast_sigmoid(accS[i][j][2] + bs) - fast_sigmoid(accK[i][j][2] + bk)),
                ACT_SCALE * kpb.y * (fast_sigmoid(accS[i][j][3] + bs) - fast_sigmoid(accK[i][j][3] + bk)));
            *reinterpret_cast<uint16_t*>(state + (size_t)r0 * KNOW_NUM + col) = lo;
            *reinterpret_cast<uint16_t*>(state + (size_t)(r0 + 8) * KNOW_NUM + col) = hi;
        }
    }
}

// ---------------------------------------------------------------------------
// Fused MLP chain: one CTA = 64 batch rows through h1 -> h2 -> h3 -> out.
// 256 threads, 8 warps as 2m x 4n (warp tile 32x32). Activations stay in
// smem (fp8, BRS chunk layout). Weights streamed 128-row x 64B sub-tiles
// through a 2-stage smem ring.
// smem map (bytes):
//   [0,      10240)  state A   (2 chunks)
//   [10240,  51200)  h1        (8 chunks)
//   [51200,  71680)  h2        (4 chunks)
//   [71680,  92160)  weight ring (2 x 10240)
//   [92160,  93184)  sred [64][4] floats
// ---------------------------------------------------------------------------
#define MC_A_OFF   0
#define MC_H1_OFF  10240
#define MC_H2_OFF  51200
#define MC_W_OFF   71680
#define MC_WSTG    10240
#define MC_SRED    92160
#define MC_DYN     93184

__device__ __forceinline__ void mc_wstage(const uint8_t* __restrict__ Bt, int K,
                                          int n0, int k0, uint32_t wb, int tid) {
#pragma unroll
    for (int i = 0; i < 2; i++) {
        int idx = tid + i * 256;              // 0..511: 128 rows x 4 sectors
        int r = idx >> 2, c4 = idx & 3;
        uint32_t off = (uint32_t)(r * BRS + c4 * 4) * 4u;
        CP_ASYNC16(wb + off, Bt + (size_t)(n0 + r) * K + k0 + c4 * 16);
    }
    CP_COMMIT();
}

// One hidden layer: dest(fp8 smem) = ACT_SCALE * tanh(INV_SCALE*acc + bias)
template <int KC, int NSUB>
__device__ __forceinline__ void mc_layer(char* dynp, uint32_t sbase,
                                         uint32_t Aoff, uint32_t Doff,
                                         const uint8_t* __restrict__ Bt, int K,
                                         const float* __restrict__ bias,
                                         int wm, int wnl, int g, int tig, int tid,
                                         uint32_t aoff0, uint32_t aoff1,
                                         uint32_t boff0, uint32_t boff1) {
    float acc[2][4][4];
#pragma unroll
    for (int i = 0; i < 2; i++)
#pragma unroll
        for (int j = 0; j < 4; j++)
#pragma unroll
            for (int q = 0; q < 4; q++) acc[i][j][q] = 0.0f;

    const uint32_t WB = sbase + MC_W_OFF;
    mc_wstage(Bt, K, 0, 0, WB, tid);
    const int T = KC * NSUB;
    for (int t = 0; t < T; t++) {
        const int ns = t / KC, c = t % KC;
        if (t + 1 < T) {
            const int t2 = t + 1;
            mc_wstage(Bt, K, (t2 / KC) * 128, (t2 % KC) * 64,
                      WB + ((t2 & 1) ? MC_WSTG : 0), tid);
            asm volatile("cp.async.wait_group 1;" ::: "memory");
        } else {
            asm volatile("cp.async.wait_group 0;" ::: "memory");
        }
        __syncthreads();

        const uint32_t As = sbase + Aoff + (uint32_t)c * CHUNK_B;
        const uint32_t Bs = WB + ((t & 1) ? MC_WSTG : 0);
        uint32_t af[2][2][4], bf[2][4][2];
#pragma unroll
        for (int kk = 0; kk < 2; kk++) {
            const uint32_t kby = kk * 32u;
            LDSM_X4(af[kk][0][0], af[kk][0][1], af[kk][0][2], af[kk][0][3], As + aoff0 + kby);
            LDSM_X4(af[kk][1][0], af[kk][1][1], af[kk][1][2], af[kk][1][3], As + aoff1 + kby);
            LDSM_X4(bf[kk][0][0], bf[kk][0][1], bf[kk][1][0], bf[kk][1][1], Bs + boff0 + kby);
            LDSM_X4(bf[kk][2][0], bf[kk][2][1], bf[kk][3][0], bf[kk][3][1], Bs + boff1 + kby);
        }
#pragma unroll
        for (int kk = 0; kk < 2; kk++) {
#pragma unroll
            for (int j = 0; j < 4; j++) {
                mma_fp8(acc[0][j], af[kk][0], bf[kk][j][0], bf[kk][j][1]);
                mma_fp8(acc[1][j], af[kk][1], bf[kk][j][0], bf[kk][j][1]);
            }
        }

        if (c == KC - 1) {
            // epilogue for this n-subtile -> dest smem (fp8 BRS layout)
#pragma unroll
            for (int i = 0; i < 2; i++) {
                const int row = wm + i * 16 + g;
#pragma unroll
                for (int j = 0; j < 4; j++) {
                    const int colL = wnl + j * 8 + tig * 2;
                    const int gcol = ns * 128 + colL;
                    float bx0 = bias[gcol], bx1 = bias[gcol + 1];
                    uint16_t lo = fp8x2(
                        ACT_SCALE * fast_tanh(INV_SCALE * acc[i][j][0] + bx0),
                        ACT_SCALE * fast_tanh(INV_SCALE * acc[i][j][1] + bx1));
                    uint16_t hi = fp8x2(
                        ACT_SCALE * fast_tanh(INV_SCALE * acc[i][j][2] + bx0),
                        ACT_SCALE * fast_tanh(INV_SCALE * acc[i][j][3] + bx1));
                    uint32_t bo = Doff + (uint32_t)(gcol >> 6) * CHUNK_B +
                                  (uint32_t)row * (BRS * 4) + (gcol & 63);
                    *reinterpret_cast<uint16_t*>(dynp + bo) = lo;
                    *reinterpret_cast<uint16_t*>(dynp + bo + 8 * BRS * 4) = hi;
                }
            }
#pragma unroll
            for (int i = 0; i < 2; i++)
#pragma unroll
                for (int j = 0; j < 4; j++)
#pragma unroll
                    for (int q = 0; q < 4; q++) acc[i][j][q] = 0.0f;
        }
        __syncthreads();
    }
}

__global__ __launch_bounds__(256, 1) void mlp_chain_kernel(
    const uint8_t* __restrict__ state,
    const uint8_t* __restrict__ W1t, const float* __restrict__ b1,
    const uint8_t* __restrict__ W2t, const float* __restrict__ b2,
    const uint8_t* __restrict__ W3t, const float* __restrict__ b3,
    const float* __restrict__ W4, const float* __restrict__ b4,
    float* __restrict__ out) {
    extern __shared__ __align__(16) char dyn[];
    const uint32_t sbase = smem_u32(dyn);
    float* sred = reinterpret_cast<float*>(dyn + MC_SRED);

    const int tid = threadIdx.x;
    const int wid = tid >> 5;
    const int lane = tid & 31;
    const int g = lane >> 2, tig = lane & 3;
    const int wm = (wid & 1) * 32;        // 2 warps in M (64 rows)
    const int wnl = (wid >> 1) * 32;      // 4 warps in N (128 cols / subtile)
    const int m0 = blockIdx.x * 64;

    const uint32_t aoff0 = (uint32_t)((wm + (lane & 15)) * BRS + (lane >> 4) * 4) * 4u;
    const uint32_t aoff1 = aoff0 + 16u * BRS * 4u;
    const uint32_t boff0 = (uint32_t)((wnl + ((lane >> 4) << 3) + (lane & 7)) * BRS +
                                      ((lane >> 3) & 1) * 4) * 4u;
    const uint32_t boff1 = boff0 + 16u * BRS * 4u;

    // Load state tile (2 chunks) into smem A region
    {
#pragma unroll
        for (int i = 0; i < 2; i++) {
            int idx = tid + i * 256;          // 0..511
            int ch = idx >> 8, r = (idx >> 2) & 63, c4 = idx & 3;
            uint32_t dst = sbase + MC_A_OFF + (uint32_t)ch * CHUNK_B +
                           (uint32_t)(r * BRS + c4 * 4) * 4u;
            CP_ASYNC16(dst, state + (size_t)(m0 + r) * KNOW_NUM + ch * 64 + c4 * 16);
        }
        CP_COMMIT();
    }

    // Layer 1: h1[64x512] = tanh(state @ W1t^T + b1); K=128 (2 chunks), 4 subtiles
    mc_layer<2, 4>(dyn, sbase, MC_A_OFF, MC_H1_OFF, W1t, KNOW_NUM, b1,
                   wm, wnl, g, tig, tid, aoff0, aoff1, boff0, boff1);

    // Layer 2: h2[64x256] = tanh(h1 @ W2t^T + b2); K=512 (8 chunks), 2 subtiles
    mc_layer<8, 2>(dyn, sbase, MC_H1_OFF, MC_H2_OFF, W2t, HIDDEN, b2,
                   wm, wnl, g, tig, tid, aoff0, aoff1, boff0, boff1);

    // Layer 3 + final: out = sigmoid(tanh(h2 @ W3t^T + b3) . W4 + b4)
    {
        float acc[2][4][4];
#pragma unroll
        for (int i = 0; i < 2; i++)
#pragma unroll
            for (int j = 0; j < 4; j++)
#pragma unroll
                for (int q = 0; q < 4; q++) acc[i][j][q] = 0.0f;

        const uint32_t WB = sbase + MC_W_OFF;
        const int KC = 4;   // K=256
        mc_wstage(W3t, HIDDEN / 2, 0, 0, WB, tid);
        for (int t = 0; t < KC; t++) {
            if (t + 1 < KC) {
                mc_wstage(W3t, HIDDEN / 2, 0, (t + 1) * 64,
                          WB + (((t + 1) & 1) ? MC_WSTG : 0), tid);
                asm volatile("cp.async.wait_group 1;" ::: "memory");
            } else {
                asm volatile("cp.async.wait_group 0;" ::: "memory");
            }
            __syncthreads();

            const uint32_t As = sbase + MC_H2_OFF + (uint32_t)t * CHUNK_B;
            const uint32_t Bs = WB + ((t & 1) ? MC_WSTG : 0);
            uint32_t af[2][2][4], bf[2][4][2];
#pragma unroll
            for (int kk = 0; kk < 2; kk++) {
                const uint32_t kby = kk * 32u;
                LDSM_X4(af[kk][0][0], af[kk][0][1], af[kk][0][2], af[kk][0][3], As + aoff0 + kby);
                LDSM_X4(af[kk][1][0], af[kk][1][1], af[kk][1][2], af[kk][1][3], As + aoff1 + kby);
                LDSM_X4(bf[kk][0][0], bf[kk][0][1], bf[kk][1][0], bf[kk][1][1], Bs + boff0 + kby);
                LDSM_X4(bf[kk][2][0], bf[kk][2][1], bf[kk][3][0], bf[kk][3][1], Bs + boff1 + kby);
            }
#pragma unroll
            for (int kk = 0; kk < 2; kk++) {
#pragma unroll
                for (int j = 0; j < 4; j++) {
                    mma_fp8(acc[0][j], af[kk][0], bf[kk][j][0], bf[kk][j][1]);
                    mma_fp8(acc[1][j], af[kk][1], bf[kk][j][0], bf[kk][j][1]);
                }
            }
            __syncthreads();
        }

        // Fused W4 dot
        float part[2][2] = {{0.0f, 0.0f}, {0.0f, 0.0f}};
#pragma unroll
        for (int i = 0; i < 2; i++) {
#pragma unroll
            for (int j = 0; j < 4; j++) {
                const int col = wnl + j * 8 + tig * 2;
                float w0 = W4[col], w1 = W4[col + 1];
                float bc0 = b3[col], bc1 = b3[col + 1];
                part[i][0] += fast_tanh(INV_SCALE * acc[i][j][0] + bc0) * w0 +
                              fast_tanh(INV_SCALE * acc[i][j][1] + bc1) * w1;
                part[i][1] += fast_tanh(INV_SCALE * acc[i][j][2] + bc0) * w0 +
                              fast_tanh(INV_SCALE * acc[i][j][3] + bc1) * w1;
            }
        }
#pragma unroll
        for (int i = 0; i < 2; i++)
#pragma unroll
            for (int h = 0; h < 2; h++) {
                part[i][h] += __shfl_xor_sync(0xFFFFFFFFu, part[i][h], 1);
                part[i][h] += __shfl_xor_sync(0xFFFFFFFFu, part[i][h], 2);
            }
        if (tig == 0) {
#pragma unroll
            for (int i = 0; i < 2; i++)
#pragma unroll
                for (int h = 0; h < 2; h++)
                    sred[(wm + i * 16 + g + h * 8) * 4 + (wid >> 1)] = part[i][h];
        }
        __syncthreads();
        if (tid < 64) {
            float s = sred[tid * 4] + sred[tid * 4 + 1] + sred[tid * 4 + 2] +
                      sred[tid * 4 + 3] + b4[0];
            out[m0 + tid] = fast_sigmoid(s);
        }
    }
}

// ---------------------------------------------------------------------------
// Launch
// ---------------------------------------------------------------------------
extern "C" void kernel_launch(void* const* d_in, const int* in_sizes, int n_in,
                              void* d_out, int out_size) {
    const float* z       = (const float*)d_in[0];
    const int*   sid     = (const int*)d_in[1];
    const int*   eid     = (const int*)d_in[2];
    const float* kp      = (const float*)d_in[3];
    const float* w_stat  = (const float*)d_in[4];
    const float* b_stat  = (const float*)d_in[5];
    const float* w_kdiff = (const float*)d_in[6];
    const float* b_kdiff = (const float*)d_in[7];
    const float* W1      = (const float*)d_in[8];
    const float* b1      = (const float*)d_in[9];
    const float* W2      = (const float*)d_in[10];
    const float* b2      = (const float*)d_in[11];
    const float* W3      = (const float*)d_in[12];
    const float* b3      = (const float*)d_in[13];
    const float* W4      = (const float*)d_in[14];
    const float* b4      = (const float*)d_in[15];
    float* out = (float*)d_out;

    uint8_t *pState, *pW1t, *pW2t, *pW3t;
    float *pKnowS, *pKnowK;
    cudaGetSymbolAddress((void**)&pState, g_state);
    cudaGetSymbolAddress((void**)&pKnowS, g_knowS);
    cudaGetSymbolAddress((void**)&pKnowK, g_knowK);
    cudaGetSymbolAddress((void**)&pW1t, g_W1t);
    cudaGetSymbolAddress((void**)&pW2t, g_W2t);
    cudaGetSymbolAddress((void**)&pW3t, g_W3t);

    const float* know = z + (size_t)(STU_NUM + PROB_NUM) * DIM;

    static bool attr_set = false;
    if (!attr_set) {
        cudaFuncSetAttribute(fused1_kernel, cudaFuncAttributeMaxDynamicSharedMemorySize, F1_DYN_SMEM);
        cudaFuncSetAttribute(mlp_chain_kernel, cudaFuncAttributeMaxDynamicSharedMemorySize, MC_DYN);
        attr_set = true;
    }

    // 1. prep: weight transposes + scaled knowledge mats
    prep_kernel<<<dim3(16, 16, 4), dim3(32, 8)>>>(W1, W2, W3, know, w_stat, w_kdiff,
                                                  pW1t, pW2t, pW3t, pKnowS, pKnowK);

    // 2. fused gather + dual GEMM + combine -> state (fp8 x64)
    fused1_kernel<<<BATCH / 64, 256, F1_DYN_SMEM>>>(z, sid, eid, pKnowS, pKnowK,
                                                    kp, b_stat, b_kdiff, pState);

    // 3. fused MLP chain (h1 -> h2 -> h3 -> out), 128 CTAs
    mlp_chain_kernel<<<BATCH / 64, 256, MC_DYN>>>(pState, pW1t, b1, pW2t, b2,
                                                  pW3t, b3, W4, b4, out);
}